// round 8
// baseline (speedup 1.0000x reference)
#include <cuda_runtime.h>
#include <cuda_bf16.h>
#include <cuda_fp8.h>
#include <cstdint>

// ============================================================================
// output = 100/512 * (#pos edges with logit<=0.5 + #neg edges with logit>0.5)
// logit = W2 . relu(W1 . relu(x_i*x_j) + b1) + b2.
// (mean of segment sums == total/NUM_GRAPHS => `batch` irrelevant; each
//  misclassified edge contributes exactly 100.)
//
// R8: fp8 e4m3 mma.sync.m16n8k32 (halves MMA count + operand smem bytes),
// TILE_M=512 / 64 rows per warp (4x less W1 re-read per edge), double-buffered
// A with gather of tile t+1 register-pipelined inside the MMA j-loop.
// Products computed in bf16 (exact gather), quantized to e4m3; accum fp32.
// ============================================================================

#define NUM_GRAPHS 512
#define HDIM 160
#define TILE_M 512
#define NTHREADS 256
#define ROWB 176              // fp8 row pitch (bytes); 44 words -> conflict-free ldsm

// ---- scratch (no cudaMalloc allowed) ----
__device__ __nv_bfloat16 g_xbf[16000000];   // 100000 x 160 bf16 = 32MB
__device__ int g_count;

// ---- dynamic SMEM layout (bytes) ----
#define OFF_A0   0                           // 512 x 176 = 90112
#define OFF_A1   90112                       // 512 x 176 = 90112
#define OFF_B    180224                      // 160 x 176 = 28160
#define OFF_BW   208384                      // float2[160] {b1,w2} = 1280
#define SMEM_TOTAL 209664

__device__ __forceinline__ uint32_t smem_u32(const void* p) {
    uint32_t a;
    asm("{ .reg .u64 t; cvta.to.shared.u64 t, %1; cvt.u32.u64 %0, t; }"
        : "=r"(a) : "l"(p));
    return a;
}

__device__ __forceinline__ void ldsm_x4(uint32_t* r, uint32_t addr) {
    asm volatile("ldmatrix.sync.aligned.m8n8.x4.shared.b16 {%0,%1,%2,%3}, [%4];"
                 : "=r"(r[0]), "=r"(r[1]), "=r"(r[2]), "=r"(r[3]) : "r"(addr));
}

__device__ __forceinline__ void ldsm_x2(uint32_t* r, uint32_t addr) {
    asm volatile("ldmatrix.sync.aligned.m8n8.x2.shared.b16 {%0,%1}, [%2];"
                 : "=r"(r[0]), "=r"(r[1]) : "r"(addr));
}

// fp8 e4m3 MMA, fp32 accum: D[16x8] += A[16x32] * B[32x8]
__device__ __forceinline__ void mma_fp8(float* d, const uint32_t* a,
                                        const uint32_t* b) {
    asm volatile(
        "mma.sync.aligned.m16n8k32.row.col.f32.e4m3.e4m3.f32 "
        "{%0,%1,%2,%3}, {%4,%5,%6,%7}, {%8,%9}, {%0,%1,%2,%3};"
        : "+f"(d[0]), "+f"(d[1]), "+f"(d[2]), "+f"(d[3])
        : "r"(a[0]), "r"(a[1]), "r"(a[2]), "r"(a[3]), "r"(b[0]), "r"(b[1]));
}

// relu(bf16x2 * bf16x2) -> e4m3x2 (as u16)
__device__ __forceinline__ unsigned short bfmr8(uint32_t a, uint32_t b) {
    __nv_bfloat162 x = *reinterpret_cast<__nv_bfloat162*>(&a);
    __nv_bfloat162 y = *reinterpret_cast<__nv_bfloat162*>(&b);
    __nv_bfloat162 z = __hmax2(__hmul2(x, y), __float2bfloat162_rn(0.0f));
    __nv_fp8x2_e4m3 p(__bfloat1622float2(z));
    return *reinterpret_cast<unsigned short*>(&p);
}

// gather mapping: it in [0,40): 8 edges x 4 chunks per iteration.
// eo = edge-in-warp (0..63), c = uint4 chunk of the bf16 x-row (0..19).
#define G_EO(it) ((lid >> 2) + (((it) & 7) << 3))
#define G_C(it)  ((((it) >> 3) << 2) + (lid & 3))

#define GLOAD(it, VA, VB) do {                                    \
    int _eo = G_EO(it);                                           \
    int _c  = G_C(it);                                            \
    int _ii, _jj;                                                 \
    if ((it) & 4) { _ii = __shfl_sync(0xFFFFFFFFu, myI1, _eo);    \
                    _jj = __shfl_sync(0xFFFFFFFFu, myJ1, _eo); }  \
    else          { _ii = __shfl_sync(0xFFFFFFFFu, myI0, _eo);    \
                    _jj = __shfl_sync(0xFFFFFFFFu, myJ0, _eo); }  \
    VA = xrows[(size_t)_ii * 20 + _c];                            \
    VB = xrows[(size_t)_jj * 20 + _c];                            \
} while (0)

#define GSTORE(it, VA, VB, DSTOFF) do {                           \
    int _eo = G_EO(it);                                           \
    int _c  = G_C(it);                                            \
    uint32_t _u0 = (uint32_t)bfmr8((VA).x, (VB).x)                \
                 | ((uint32_t)bfmr8((VA).y, (VB).y) << 16);       \
    uint32_t _u1 = (uint32_t)bfmr8((VA).z, (VB).z)                \
                 | ((uint32_t)bfmr8((VA).w, (VB).w) << 16);       \
    *reinterpret_cast<uint2*>(smem + (DSTOFF) + _eo * ROWB + _c * 8) = \
        make_uint2(_u0, _u1);                                     \
} while (0)

// ============================================================================
// Kernel 0: convert x -> bf16 scratch, zero counter
// ============================================================================
__global__ void cvt_kernel(const float* __restrict__ x, int n4) {
    if (blockIdx.x == 0 && threadIdx.x == 0) g_count = 0;
    int stride = gridDim.x * blockDim.x;
    uint2* out = reinterpret_cast<uint2*>(g_xbf);
    const float4* in = reinterpret_cast<const float4*>(x);
    for (int i = blockIdx.x * blockDim.x + threadIdx.x; i < n4; i += stride) {
        float4 v = in[i];
        __nv_bfloat162 p0 = __floats2bfloat162_rn(v.x, v.y);
        __nv_bfloat162 p1 = __floats2bfloat162_rn(v.z, v.w);
        uint2 o;
        o.x = *reinterpret_cast<uint32_t*>(&p0);
        o.y = *reinterpret_cast<uint32_t*>(&p1);
        out[i] = o;
    }
}

// ============================================================================
// Kernel 1: persistent fused edge-MLP + misclassification count
// ============================================================================
__global__ void __launch_bounds__(NTHREADS, 1)
gae_main_kernel(const int* __restrict__ pos, const int* __restrict__ neg,
                const float* __restrict__ W1, const float* __restrict__ b1,
                const float* __restrict__ W2, const float* __restrict__ b2,
                int Ep, int En) {
    extern __shared__ char smem[];
    const uint32_t sb = smem_u32(smem);
    const int tid = threadIdx.x;
    const int wid = tid >> 5;
    const int lid = tid & 31;
    const int Etot = Ep + En;
    const int ntiles = (Etot + TILE_M - 1) / TILE_M;

    // --- W1 -> SMEM B [160 rows x 176B pitch], f32 -> e4m3 ---
    {
        const float4* w1v = reinterpret_cast<const float4*>(W1);
        #pragma unroll 5
        for (int it = 0; it < 25; ++it) {
            int idx = it * NTHREADS + tid;        // 0..6399 float4s
            int n  = idx / 40;                    // W1 row (N) 0..159
            int kc = idx - n * 40;                // float4 chunk 0..39
            float4 w = w1v[idx];
            __nv_fp8x2_e4m3 p0(make_float2(w.x, w.y));
            __nv_fp8x2_e4m3 p1(make_float2(w.z, w.w));
            uint32_t u = (uint32_t)*reinterpret_cast<unsigned short*>(&p0)
                       | ((uint32_t)*reinterpret_cast<unsigned short*>(&p1) << 16);
            *reinterpret_cast<uint32_t*>(smem + OFF_B + n * ROWB + kc * 4) = u;
        }
    }
    if (tid < HDIM) {
        reinterpret_cast<float2*>(smem + OFF_BW)[tid] = make_float2(b1[tid], W2[tid]);
    }

    const float2* sbw = reinterpret_cast<const float2*>(smem + OFF_BW);
    const uint4* xrows = reinterpret_cast<const uint4*>(g_xbf);  // 20 uint4/row
    const float b2v = b2[0];

    // ldmatrix per-thread address components
    const uint32_t aoff = (uint32_t)((wid * 64 + ((lid >> 3) & 1) * 8 + (lid & 7)) * ROWB
                                     + (lid >> 4) * 16);
    const uint32_t bBase4 = sb + OFF_B
        + (uint32_t)((lid & 7) * ROWB) + (uint32_t)((lid >> 3) * 16);
    const uint32_t bBase2 = sb + OFF_B
        + (uint32_t)((lid & 7) * ROWB) + (uint32_t)(((lid >> 3) & 1) * 16) + 128u;

    int cnt = 0;
    int tile = blockIdx.x;
    int buf = 0;

    __syncthreads();                           // W1/BW ready

    if (tile < ntiles) {
        // ---- prologue: gather tile `tile` into buf0 ----
        {
            int g = tile * TILE_M + wid * 64 + lid;
            int myI0 = 0, myJ0 = 0, myI1 = 0, myJ1 = 0;
            if (g < Etot) {
                if (g < Ep) { myI0 = pos[g]; myJ0 = pos[g + Ep]; }
                else        { int q = g - Ep; myI0 = neg[q]; myJ0 = neg[q + En]; }
            }
            int g1 = g + 32;
            if (g1 < Etot) {
                if (g1 < Ep) { myI1 = pos[g1]; myJ1 = pos[g1 + Ep]; }
                else         { int q = g1 - Ep; myI1 = neg[q]; myJ1 = neg[q + En]; }
            }
            const uint32_t dstOff = OFF_A0 + (uint32_t)(wid * 64 * ROWB);
            #pragma unroll 4
            for (int it = 0; it < 40; ++it) {
                uint4 va, vb;
                GLOAD(it, va, vb);
                GSTORE(it, va, vb, dstOff);
            }
        }
        __syncthreads();

        for (; tile < ntiles; tile += gridDim.x) {
            // ---- next-tile edge indices (register-resident, 64/warp) ----
            const int nt = tile + gridDim.x;
            const bool gat = (nt < ntiles);
            int myI0 = 0, myJ0 = 0, myI1 = 0, myJ1 = 0;
            if (gat) {
                int g = nt * TILE_M + wid * 64 + lid;
                if (g < Etot) {
                    if (g < Ep) { myI0 = pos[g]; myJ0 = pos[g + Ep]; }
                    else        { int q = g - Ep; myI0 = neg[q]; myJ0 = neg[q + En]; }
                }
                int g1 = g + 32;
                if (g1 < Etot) {
                    if (g1 < Ep) { myI1 = pos[g1]; myJ1 = pos[g1 + Ep]; }
                    else         { int q = g1 - Ep; myI1 = neg[q]; myJ1 = neg[q + En]; }
                }
            }
            const uint32_t aBase = sb + (buf ? OFF_A1 : OFF_A0) + aoff;
            const uint32_t dstOff = (buf ? OFF_A0 : OFF_A1)
                                  + (uint32_t)(wid * 64 * ROWB);

            // ---- A fragments: this warp's 64 rows, all K (80 regs) ----
            uint32_t af[4][5][4];
            #pragma unroll
            for (int m = 0; m < 4; ++m)
                #pragma unroll
                for (int s = 0; s < 5; ++s)
                    ldsm_x4(af[m][s], aBase + (uint32_t)(m * 16 * ROWB + s * 32));

            // ---- depth-2 gather prefetch ----
            uint4 va0, vb0, va1, vb1;
            if (gat) { GLOAD(0, va0, vb0); GLOAD(1, va1, vb1); }

            float acc[4][2] = {{0.f,0.f},{0.f,0.f},{0.f,0.f},{0.f,0.f}};

            #pragma unroll 1
            for (int j = 0; j < 20; ++j) {
                // B fragments for 5 k32-steps: 2x ldsm.x4 + 1x ldsm.x2
                uint32_t br[10];
                const uint32_t bj4 = bBase4 + (uint32_t)(j * 8 * ROWB);
                ldsm_x4(br,     bj4);          // k-steps 0,1
                ldsm_x4(br + 4, bj4 + 64);     // k-steps 2,3
                ldsm_x2(br + 8, bBase2 + (uint32_t)(j * 8 * ROWB)); // k-step 4

                float d[4][4] = {{0.f,0.f,0.f,0.f},{0.f,0.f,0.f,0.f},
                                 {0.f,0.f,0.f,0.f},{0.f,0.f,0.f,0.f}};
                #pragma unroll
                for (int s = 0; s < 5; ++s)
                    #pragma unroll
                    for (int m = 0; m < 4; ++m)
                        mma_fp8(d[m], af[m][s], br + s * 2);

                if (gat) {
                    GSTORE(2 * j, va0, vb0, dstOff);
                    if (2 * j + 2 < 40) GLOAD(2 * j + 2, va0, vb0);
                    GSTORE(2 * j + 1, va1, vb1, dstOff);
                    if (2 * j + 3 < 40) GLOAD(2 * j + 3, va1, vb1);
                }

                const int n0 = j * 8 + (lid & 3) * 2;
                const float2 bw0 = sbw[n0];
                const float2 bw1 = sbw[n0 + 1];
                #pragma unroll
                for (int m = 0; m < 4; ++m) {
                    acc[m][0] += fmaxf(d[m][0] + bw0.x, 0.0f) * bw0.y
                               + fmaxf(d[m][1] + bw1.x, 0.0f) * bw1.y;
                    acc[m][1] += fmaxf(d[m][2] + bw0.x, 0.0f) * bw0.y
                               + fmaxf(d[m][3] + bw1.x, 0.0f) * bw1.y;
                }
            }

            // ---- reduce 4 lanes/row, threshold, count ----
            #pragma unroll
            for (int m = 0; m < 4; ++m) {
                #pragma unroll
                for (int h = 0; h < 2; ++h) {
                    float a = acc[m][h];
                    a += __shfl_xor_sync(0xFFFFFFFFu, a, 1);
                    a += __shfl_xor_sync(0xFFFFFFFFu, a, 2);
                    if ((lid & 3) == 0) {
                        int r = tile * TILE_M + wid * 64 + m * 16 + (lid >> 2) + h * 8;
                        if (r < Etot) {
                            bool pred = (a + b2v) > 0.5f;
                            if (pred != (r < Ep)) cnt++;
                        }
                    }
                }
            }
            buf ^= 1;
            __syncthreads();   // next A fully written; current A consumed
        }
    }

    // ---- reduce counts ----
    #pragma unroll
    for (int o = 16; o; o >>= 1) cnt += __shfl_xor_sync(0xFFFFFFFFu, cnt, o);
    if (lid == 0 && cnt) atomicAdd(&g_count, cnt);
}

// ============================================================================
// Kernel 2: finalize scalar
// ============================================================================
__global__ void fin_kernel(float* out) {
    out[0] = (float)((double)g_count * 100.0 / (double)NUM_GRAPHS);
}

// ============================================================================
extern "C" void kernel_launch(void* const* d_in, const int* in_sizes, int n_in,
                              void* d_out, int out_size) {
    const float* x   = (const float*)d_in[0];
    const int*   pos = (const int*)  d_in[1];
    const int*   neg = (const int*)  d_in[2];
    // d_in[3] = batch (irrelevant: mean of segment sums == total/512)
    const float* W1  = (const float*)d_in[4];
    const float* b1  = (const float*)d_in[5];
    const float* W2  = (const float*)d_in[6];
    const float* b2  = (const float*)d_in[7];

    int Ep = in_sizes[1] / 2;
    int En = in_sizes[2] / 2;
    int n4 = in_sizes[0] / 4;

    static int configured = 0;
    if (!configured) {
        cudaFuncSetAttribute(gae_main_kernel,
                             cudaFuncAttributeMaxDynamicSharedMemorySize,
                             SMEM_TOTAL);
        configured = 1;
    }

    int sms = 148;
    cudaDeviceGetAttribute(&sms, cudaDevAttrMultiProcessorCount, 0);
    if (sms <= 0) sms = 148;

    cvt_kernel<<<1024, 256>>>(x, n4);
    gae_main_kernel<<<sms, NTHREADS, SMEM_TOTAL>>>(pos, neg, W1, b1, W2, b2, Ep, En);
    fin_kernel<<<1, 1>>>((float*)d_out);
}

// round 9
// speedup vs baseline: 1.2304x; 1.2304x over previous
#include <cuda_runtime.h>
#include <cuda_bf16.h>
#include <cstdint>

// ============================================================================
// output = 100/512 * (#pos edges with logit<=0.5 + #neg edges with logit>0.5)
// logit = W2 . relu(W1 . relu(x_i*x_j) + b1) + b2.
// (mean of segment sums == total/NUM_GRAPHS => `batch` irrelevant; each
//  misclassified edge contributes exactly 100.)
//
// R9 = R7 (bf16 m16n8k16, TILE_M=256, double-buffered A, pipelined gather)
//  + split-K accumulators (4 independent MMA chains/warp, RAW distance 4)
//  + B-fragment double buffering across j (ldsm latency hidden under MMAs).
// ============================================================================

#define NUM_GRAPHS 512
#define HDIM 160
#define TILE_M 256
#define NTHREADS 256
#define ROWB 336              // padded row pitch (bytes): conflict-free ldsm

// ---- scratch (no cudaMalloc allowed) ----
__device__ __nv_bfloat16 g_xbf[16000000];   // 100000 x 160 bf16 = 32MB
__device__ int g_count;

// ---- dynamic SMEM layout (bytes) ----
#define OFF_A0   0                          // 256 x 336 = 86016
#define OFF_A1   86016                      // 256 x 336 = 86016
#define OFF_B    172032                     // 160 x 336 = 53760
#define OFF_BW   225792                     // float2[160] {b1,w2} = 1280
#define SMEM_TOTAL 227072

__device__ __forceinline__ uint32_t smem_u32(const void* p) {
    uint32_t a;
    asm("{ .reg .u64 t; cvta.to.shared.u64 t, %1; cvt.u32.u64 %0, t; }"
        : "=r"(a) : "l"(p));
    return a;
}

__device__ __forceinline__ void ldsm_x4(uint32_t* r, uint32_t addr) {
    asm volatile("ldmatrix.sync.aligned.m8n8.x4.shared.b16 {%0,%1,%2,%3}, [%4];"
                 : "=r"(r[0]), "=r"(r[1]), "=r"(r[2]), "=r"(r[3]) : "r"(addr));
}

__device__ __forceinline__ void mma16816(float* d, const uint32_t* a,
                                         const uint32_t* b) {
    asm volatile(
        "mma.sync.aligned.m16n8k16.row.col.f32.bf16.bf16.f32 "
        "{%0,%1,%2,%3}, {%4,%5,%6,%7}, {%8,%9}, {%0,%1,%2,%3};"
        : "+f"(d[0]), "+f"(d[1]), "+f"(d[2]), "+f"(d[3])
        : "r"(a[0]), "r"(a[1]), "r"(a[2]), "r"(a[3]), "r"(b[0]), "r"(b[1]));
}

// bf16x2 multiply + relu, packed
__device__ __forceinline__ uint32_t bfmr(uint32_t a, uint32_t b) {
    __nv_bfloat162 x = *reinterpret_cast<__nv_bfloat162*>(&a);
    __nv_bfloat162 y = *reinterpret_cast<__nv_bfloat162*>(&b);
    __nv_bfloat162 z = __hmul2(x, y);
    const __nv_bfloat162 zero = __float2bfloat162_rn(0.0f);
    z = __hmax2(z, zero);
    return *reinterpret_cast<uint32_t*>(&z);
}

// gather addressing: per warp, 32 next-tile edges; lane groups of 4 read 64B
// contiguous per edge. it in [0,20): eo = edge-in-warp, ch = uint4 chunk.
#define G_EO(it) ((lid >> 2) + (((it) / 5) << 3))
#define G_CH(it) (((it) % 5) * 4 + (lid & 3))

#define GLOAD(it, VA, VB) do {                                   \
    int _eo = G_EO(it);                                          \
    int _ch = G_CH(it);                                          \
    int _ii = __shfl_sync(0xFFFFFFFFu, myI, _eo);                \
    int _jj = __shfl_sync(0xFFFFFFFFu, myJ, _eo);                \
    VA = xrows[(size_t)_ii * 20 + _ch];                          \
    VB = xrows[(size_t)_jj * 20 + _ch];                          \
} while (0)

#define GSTORE(it, VA, VB, DSTOFF) do {                          \
    int _eo = G_EO(it);                                          \
    int _ch = G_CH(it);                                          \
    uint4 _r;                                                    \
    _r.x = bfmr((VA).x, (VB).x);                                 \
    _r.y = bfmr((VA).y, (VB).y);                                 \
    _r.z = bfmr((VA).z, (VB).z);                                 \
    _r.w = bfmr((VA).w, (VB).w);                                 \
    *reinterpret_cast<uint4*>(smem + (DSTOFF) + _eo * ROWB + _ch * 16) = _r; \
} while (0)

// load the 20 B-fragment regs for column-chunk j (5x ldsm.x4)
__device__ __forceinline__ void load_b20(uint32_t* br, uint32_t bBase, int j) {
    const uint32_t bj = bBase + (uint32_t)(j * 8 * ROWB);
    #pragma unroll
    for (int t = 0; t < 5; ++t) ldsm_x4(br + 4 * t, bj + (uint32_t)(t * 64));
}

// 20 MMAs into 4 independent accumulator chains (RAW distance 4)
__device__ __forceinline__ void mma20(float dd[2][2][4],
                                      const uint32_t af[2][10][4],
                                      const uint32_t* br) {
    #pragma unroll
    for (int s = 0; s < 10; ++s) {
        const uint32_t* b = br + ((s >> 1) << 2) + ((s & 1) << 1);
        mma16816(dd[0][s & 1], af[0][s], b);
        mma16816(dd[1][s & 1], af[1][s], b);
    }
}

__device__ __forceinline__ void epi(float dd[2][2][4], float acc[2][2],
                                    const float2* sbw, int j, int lid) {
    const int n0 = j * 8 + (lid & 3) * 2;
    const float2 bw0 = sbw[n0];
    const float2 bw1 = sbw[n0 + 1];
    #pragma unroll
    for (int m = 0; m < 2; ++m) {
        float d0 = dd[m][0][0] + dd[m][1][0];
        float d1 = dd[m][0][1] + dd[m][1][1];
        float d2 = dd[m][0][2] + dd[m][1][2];
        float d3 = dd[m][0][3] + dd[m][1][3];
        acc[m][0] += fmaxf(d0 + bw0.x, 0.0f) * bw0.y
                   + fmaxf(d1 + bw1.x, 0.0f) * bw1.y;
        acc[m][1] += fmaxf(d2 + bw0.x, 0.0f) * bw0.y
                   + fmaxf(d3 + bw1.x, 0.0f) * bw1.y;
    }
}

#define DD_ZERO(dd) do {                                         \
    _Pragma("unroll")                                            \
    for (int _m = 0; _m < 2; ++_m)                               \
        _Pragma("unroll")                                        \
        for (int _h = 0; _h < 2; ++_h)                           \
            _Pragma("unroll")                                    \
            for (int _r = 0; _r < 4; ++_r) (dd)[_m][_h][_r] = 0.0f; \
} while (0)

// ============================================================================
// Kernel 0: convert x -> bf16 scratch, zero counter
// ============================================================================
__global__ void cvt_kernel(const float* __restrict__ x, int n4) {
    if (blockIdx.x == 0 && threadIdx.x == 0) g_count = 0;
    int stride = gridDim.x * blockDim.x;
    uint2* out = reinterpret_cast<uint2*>(g_xbf);
    const float4* in = reinterpret_cast<const float4*>(x);
    for (int i = blockIdx.x * blockDim.x + threadIdx.x; i < n4; i += stride) {
        float4 v = in[i];
        __nv_bfloat162 p0 = __floats2bfloat162_rn(v.x, v.y);
        __nv_bfloat162 p1 = __floats2bfloat162_rn(v.z, v.w);
        uint2 o;
        o.x = *reinterpret_cast<uint32_t*>(&p0);
        o.y = *reinterpret_cast<uint32_t*>(&p1);
        out[i] = o;
    }
}

// ============================================================================
// Kernel 1: persistent fused edge-MLP + misclassification count
// ============================================================================
__global__ void __launch_bounds__(NTHREADS, 1)
gae_main_kernel(const int* __restrict__ pos, const int* __restrict__ neg,
                const float* __restrict__ W1, const float* __restrict__ b1,
                const float* __restrict__ W2, const float* __restrict__ b2,
                int Ep, int En) {
    extern __shared__ char smem[];
    const uint32_t sb = smem_u32(smem);
    const int tid = threadIdx.x;
    const int wid = tid >> 5;
    const int lid = tid & 31;
    const int Etot = Ep + En;
    const int ntiles = (Etot + TILE_M - 1) / TILE_M;

    // --- load W1 -> SMEM B [160 rows x 336B pitch], f32 -> bf16 ---
    {
        const float4* w1v = reinterpret_cast<const float4*>(W1);
        #pragma unroll 5
        for (int it = 0; it < 25; ++it) {
            int idx = it * NTHREADS + tid;        // 0..6399
            int n  = idx / 40;                    // N row 0..159
            int kc = idx - n * 40;                // float4 chunk 0..39
            float4 w = w1v[idx];
            __nv_bfloat162 p0 = __floats2bfloat162_rn(w.x, w.y);
            __nv_bfloat162 p1 = __floats2bfloat162_rn(w.z, w.w);
            uint2 v;
            v.x = *reinterpret_cast<uint32_t*>(&p0);
            v.y = *reinterpret_cast<uint32_t*>(&p1);
            *reinterpret_cast<uint2*>(smem + OFF_B + n * ROWB + kc * 8) = v;
        }
    }
    if (tid < HDIM) {
        reinterpret_cast<float2*>(smem + OFF_BW)[tid] = make_float2(b1[tid], W2[tid]);
    }

    const float2* sbw = reinterpret_cast<const float2*>(smem + OFF_BW);
    const uint4* xrows = reinterpret_cast<const uint4*>(g_xbf);  // 20 uint4/row
    const float b2v = b2[0];

    // per-thread ldmatrix address components
    const uint32_t aoff = (uint32_t)((wid * 32 + ((lid >> 3) & 1) * 8 + (lid & 7)) * ROWB
                                     + (lid >> 4) * 16);
    const uint32_t bBase = sb + OFF_B
        + (uint32_t)((lid & 7) * ROWB) + (uint32_t)((lid >> 3) * 16);

    int cnt = 0;
    int tile = blockIdx.x;
    int buf = 0;                               // buffer holding CURRENT tile

    __syncthreads();                           // W1/BW ready

    if (tile < ntiles) {
        // ---- prologue: gather tile `tile` into buf0 ----
        {
            int g = tile * TILE_M + wid * 32 + lid;
            int myI = 0, myJ = 0;
            if (g < Etot) {
                if (g < Ep) { myI = pos[g];      myJ = pos[g + Ep]; }
                else        { int q = g - Ep; myI = neg[q]; myJ = neg[q + En]; }
            }
            const uint32_t dstOff = OFF_A0 + (uint32_t)(wid * 32 * ROWB);
            #pragma unroll 4
            for (int it = 0; it < 20; ++it) {
                uint4 va, vb;
                GLOAD(it, va, vb);
                GSTORE(it, va, vb, dstOff);
            }
        }
        __syncthreads();

        for (; tile < ntiles; tile += gridDim.x) {
            // ---- next-tile edge indices (register-resident, per warp slice) ----
            const int nt = tile + gridDim.x;
            const bool gat = (nt < ntiles);
            int myI = 0, myJ = 0;
            if (gat) {
                int g = nt * TILE_M + wid * 32 + lid;
                if (g < Etot) {
                    if (g < Ep) { myI = pos[g];      myJ = pos[g + Ep]; }
                    else        { int q = g - Ep; myI = neg[q]; myJ = neg[q + En]; }
                }
            }
            const uint32_t aBase = sb + (buf ? OFF_A1 : OFF_A0) + aoff;
            const uint32_t dstOff = (buf ? OFF_A0 : OFF_A1) + (uint32_t)(wid * 32 * ROWB);

            // ---- A fragments: this warp's 32 rows, all K (80 regs) ----
            uint32_t af[2][10][4];
            #pragma unroll
            for (int m = 0; m < 2; ++m)
                #pragma unroll
                for (int s = 0; s < 10; ++s)
                    ldsm_x4(af[m][s], aBase + (uint32_t)(m * 16 * ROWB + s * 32));

            // ---- depth-2 gather pipeline prefetch ----
            uint4 va[2], vb[2];
            if (gat) { GLOAD(0, va[0], vb[0]); GLOAD(1, va[1], vb[1]); }

            float acc[2][2] = {{0.0f, 0.0f}, {0.0f, 0.0f}};

            // ---- j-loop: B-frag double buffered, 2 columns-chunks/iter ----
            uint32_t brA[20], brB[20];
            load_b20(brA, bBase, 0);

            #pragma unroll 2
            for (int jj = 0; jj < 10; ++jj) {
                const int j0 = 2 * jj, j1 = j0 + 1;
                float dd[2][2][4];

                // even j: consume brA, prefetch j1 into brB
                load_b20(brB, bBase, j1);
                DD_ZERO(dd);
                mma20(dd, af, brA);
                if (gat) {
                    GSTORE(j0, va[0], vb[0], dstOff);
                    if (j0 + 2 < 20) GLOAD(j0 + 2, va[0], vb[0]);
                }
                epi(dd, acc, sbw, j0, lid);

                // odd j: consume brB, prefetch j0+2 into brA
                if (jj < 9) load_b20(brA, bBase, j0 + 2);
                DD_ZERO(dd);
                mma20(dd, af, brB);
                if (gat) {
                    GSTORE(j1, va[1], vb[1], dstOff);
                    if (j1 + 2 < 20) GLOAD(j1 + 2, va[1], vb[1]);
                }
                epi(dd, acc, sbw, j1, lid);
            }

            // ---- reduce 4 lanes/row, threshold, count ----
            #pragma unroll
            for (int m = 0; m < 2; ++m) {
                #pragma unroll
                for (int h = 0; h < 2; ++h) {
                    float a = acc[m][h];
                    a += __shfl_xor_sync(0xFFFFFFFFu, a, 1);
                    a += __shfl_xor_sync(0xFFFFFFFFu, a, 2);
                    if ((lid & 3) == 0) {
                        int r = tile * TILE_M + wid * 32 + m * 16 + (lid >> 2) + h * 8;
                        if (r < Etot) {
                            bool pred = (a + b2v) > 0.5f;
                            if (pred != (r < Ep)) cnt++;
                        }
                    }
                }
            }
            buf ^= 1;
            __syncthreads();   // next-tile A fully written; current A consumed
        }
    }

    // ---- reduce counts ----
    #pragma unroll
    for (int o = 16; o; o >>= 1) cnt += __shfl_xor_sync(0xFFFFFFFFu, cnt, o);
    if (lid == 0 && cnt) atomicAdd(&g_count, cnt);
}

// ============================================================================
// Kernel 2: finalize scalar
// ============================================================================
__global__ void fin_kernel(float* out) {
    out[0] = (float)((double)g_count * 100.0 / (double)NUM_GRAPHS);
}

// ============================================================================
extern "C" void kernel_launch(void* const* d_in, const int* in_sizes, int n_in,
                              void* d_out, int out_size) {
    const float* x   = (const float*)d_in[0];
    const int*   pos = (const int*)  d_in[1];
    const int*   neg = (const int*)  d_in[2];
    // d_in[3] = batch (irrelevant: mean of segment sums == total/512)
    const float* W1  = (const float*)d_in[4];
    const float* b1  = (const float*)d_in[5];
    const float* W2  = (const float*)d_in[6];
    const float* b2  = (const float*)d_in[7];

    int Ep = in_sizes[1] / 2;
    int En = in_sizes[2] / 2;
    int n4 = in_sizes[0] / 4;

    static int configured = 0;
    if (!configured) {
        cudaFuncSetAttribute(gae_main_kernel,
                             cudaFuncAttributeMaxDynamicSharedMemorySize,
                             SMEM_TOTAL);
        configured = 1;
    }

    int sms = 148;
    cudaDeviceGetAttribute(&sms, cudaDevAttrMultiProcessorCount, 0);
    if (sms <= 0) sms = 148;

    cvt_kernel<<<1024, 256>>>(x, n4);
    gae_main_kernel<<<sms, NTHREADS, SMEM_TOTAL>>>(pos, neg, W1, b1, W2, b2, Ep, En);
    fin_kernel<<<1, 1>>>((float*)d_out);
}